// round 14
// baseline (speedup 1.0000x reference)
#include <cuda_runtime.h>
#include <math_constants.h>

#define BSZ      1024
#define KCOLS    66560              // BSZ + 65536
#define KV4      (KCOLS / 4)        // 16640 float4 per row
#define HALF_F4  (KV4 / 2)          // 8320 float4 per half-row
#define NTHREADS 256
#define NWARPS   (NTHREADS / 32)
#define NBATCH   4                  // 4 batches x 8 float4 = 32/thread (8192)
#define HREM     (HALF_F4 - NBATCH * 8 * NTHREADS)  // 128 remainder float4
#define VCAP_L   768                // per-CTA smem candidate slots (~205 expected)
#define RCAP     1536               // per-row global candidate slots (= 2*VCAP_L)
#define TCAND    2.5f

__device__ float    g_halfS[2 * BSZ];       // per-half partial sums (own slots)
__device__ float4   g_candv[BSZ * RCAP];    // per-row candidate vectors
__device__ int      g_candi[BSZ * RCAP];    // their float4 indices
__device__ int      g_candn[BSZ];           // per-row candidate counts (zero-init)
__device__ int      g_rowdone[BSZ];         // per-row completion counters
__device__ float    g_row_loss[BSZ];
__device__ unsigned g_done = 0;             // finished-row counter

__global__ __launch_bounds__(NTHREADS, 5) void wl_row_kernel(const float* __restrict__ logits,
                                                             float* __restrict__ out)
{
    const int row  = (int)(blockIdx.x >> 1);
    const int half = (int)(blockIdx.x & 1);
    const float4* __restrict__ rp =
        reinterpret_cast<const float4*>(logits + (size_t)row * KCOLS);
    const int hbase = half * HALF_F4;

    __shared__ __align__(16) float4 s_vc[VCAP_L];   // local capture (12 KB)
    __shared__ int   s_vi[VCAP_L];                  // local indices (3 KB)
    __shared__ int   s_cnt, s_base;
    __shared__ float s_sum[NWARPS];
    __shared__ float s_max[NWARPS];
    __shared__ float s_par[4];                      // inv, m, dl, fast-flag
    __shared__ int   s_fin, s_last;

    const int tid = threadIdx.x;
    if (tid == 0) s_cnt = 0;
    __syncthreads();

    // ---- Pass 1 over this half: R7 engine — 8-deep LDG.128, smem ATOMS capture -
    float a0 = 0.f, a1 = 0.f, a2 = 0.f, a3 = 0.f;

    #define WL_DO(X, VIDX)                                                      \
    {                                                                           \
        a0 += __expf((X).x); a1 += __expf((X).y);                               \
        a2 += __expf((X).z); a3 += __expf((X).w);                               \
        float mx4 = fmaxf(fmaxf((X).x, (X).y), fmaxf((X).z, (X).w));            \
        if (mx4 >= TCAND) {                                                     \
            int p = atomicAdd(&s_cnt, 1);                                       \
            if (p < VCAP_L) { s_vc[p] = (X); s_vi[p] = (VIDX); }                \
        }                                                                       \
    }

    #pragma unroll 1
    for (int b = 0; b < NBATCH; b++) {
        const int vb = hbase + tid + b * (8 * NTHREADS);
        float4 x0 = rp[vb];
        float4 x1 = rp[vb + 1 * NTHREADS];
        float4 x2 = rp[vb + 2 * NTHREADS];
        float4 x3 = rp[vb + 3 * NTHREADS];
        float4 x4 = rp[vb + 4 * NTHREADS];
        float4 x5 = rp[vb + 5 * NTHREADS];
        float4 x6 = rp[vb + 6 * NTHREADS];
        float4 x7 = rp[vb + 7 * NTHREADS];
        WL_DO(x0, vb)
        WL_DO(x1, vb + 1 * NTHREADS)
        WL_DO(x2, vb + 2 * NTHREADS)
        WL_DO(x3, vb + 3 * NTHREADS)
        WL_DO(x4, vb + 4 * NTHREADS)
        WL_DO(x5, vb + 5 * NTHREADS)
        WL_DO(x6, vb + 6 * NTHREADS)
        WL_DO(x7, vb + 7 * NTHREADS)
    }
    if (tid < HREM) {                       // remainder: 128 float4
        const int v = hbase + NBATCH * 8 * NTHREADS + tid;
        float4 x = rp[v];
        WL_DO(x, v)
    }
    #undef WL_DO

    float sum = (a0 + a1) + (a2 + a3);
    #pragma unroll
    for (int o = 16; o; o >>= 1) sum += __shfl_xor_sync(0xffffffffu, sum, o);
    if ((tid & 31) == 0) s_sum[tid >> 5] = sum;
    __syncthreads();

    // ---- Bulk flush: ONE global atomic per CTA, parallel copy ------------------
    const int cnt = s_cnt;
    if (tid == 0) {
        float Sh = 0.f;
        #pragma unroll
        for (int i = 0; i < NWARPS; i++) Sh += s_sum[i];
        g_halfS[2 * row + half] = Sh;
        // local overflow poisons the row count -> guarantees robust fallback
        int addn = (cnt <= VCAP_L) ? cnt : (RCAP + 1);
        s_base = (addn > 0) ? atomicAdd(&g_candn[row], addn) : 0;
    }
    __syncthreads();
    {
        const int ncopy = min(cnt, VCAP_L);
        const int base  = s_base;
        for (int i = tid; i < ncopy; i += NTHREADS) {
            const int idx = base + i;
            if (idx < RCAP) {
                g_candv[(size_t)row * RCAP + idx] = s_vc[i];
                g_candi[(size_t)row * RCAP + idx] = s_vi[i];
            }
        }
    }

    if (tid == 0) {
        __threadfence();                    // publish S, candidates, count
        int t = atomicAdd(&g_rowdone[row], 1);
        s_fin = (t == 1);                   // second half-CTA finishes the row
    }
    __syncthreads();
    if (!s_fin) return;

    // ---- Finisher: this row's loss from L2-resident candidates ----------------
    const int cnt_raw = *((volatile int*)&g_candn[row]);
    const int ncv     = min(cnt_raw, RCAP);
    const float4* __restrict__ cv = &g_candv[(size_t)row * RCAP];
    const int*    __restrict__ ci = &g_candi[(size_t)row * RCAP];

    float mxo = -CUDART_INF_F;              // exact off-diag max over candidates
    for (int i = tid; i < ncv; i += NTHREADS) {
        float4 x = __ldcg(&cv[i]);
        const int base = __ldcg(&ci[i]) * 4;
        if (x.x >= TCAND && base + 0 != row) mxo = fmaxf(mxo, x.x);
        if (x.y >= TCAND && base + 1 != row) mxo = fmaxf(mxo, x.y);
        if (x.z >= TCAND && base + 2 != row) mxo = fmaxf(mxo, x.z);
        if (x.w >= TCAND && base + 3 != row) mxo = fmaxf(mxo, x.w);
    }
    #pragma unroll
    for (int o = 16; o; o >>= 1) mxo = fmaxf(mxo, __shfl_xor_sync(0xffffffffu, mxo, o));
    if ((tid & 31) == 0) s_max[tid >> 5] = mxo;
    __syncthreads();

    if (tid == 0) {
        float M = -CUDART_INF_F;
        #pragma unroll
        for (int i = 0; i < NWARPS; i++) M = fmaxf(M, s_max[i]);
        float S = __ldcg(&g_halfS[2 * row]) + __ldcg(&g_halfS[2 * row + 1]);
        float dl = logits[(size_t)row * KCOLS + row];
        float neg_mean = (S - __expf(dl)) * (1.0f / (float)(KCOLS - 1));
        float inv = 1.0f / neg_mean;
        // g(l)=l*exp(l)*inv monotone for l >= -1; M >= TCAND > 0 on fast path,
        // so g(M) is the EXACT off-diag max of u. Row max m = max(g(M), dl).
        float gmo = M * __expf(M) * inv;
        float m   = fmaxf(gmo, dl);
        float gT  = TCAND * __expf(TCAND) * inv;
        bool fast = (M >= TCAND) && (neg_mean > 0.f) &&
                    (gT <= m - 30.f) && (cnt_raw <= RCAP);
        s_par[0] = inv; s_par[1] = m; s_par[2] = dl; s_par[3] = fast ? 1.f : 0.f;
    }
    __syncthreads();

    const float inv = s_par[0], m = s_par[1], dl = s_par[2];
    const bool  fastp = (s_par[3] != 0.f);

    if (fastp) {
        float sl = 0.f;
        for (int i = tid; i < ncv; i += NTHREADS) {
            float4 x = __ldcg(&cv[i]);
            const int base = __ldcg(&ci[i]) * 4;
            if (x.x >= TCAND && base + 0 != row) sl += __expf(x.x * __expf(x.x) * inv - m);
            if (x.y >= TCAND && base + 1 != row) sl += __expf(x.y * __expf(x.y) * inv - m);
            if (x.z >= TCAND && base + 2 != row) sl += __expf(x.z * __expf(x.z) * inv - m);
            if (x.w >= TCAND && base + 3 != row) sl += __expf(x.w * __expf(x.w) * inv - m);
        }
        #pragma unroll
        for (int o = 16; o; o >>= 1) sl += __shfl_xor_sync(0xffffffffu, sl, o);
        if ((tid & 31) == 0) s_sum[tid >> 5] = sl;
        __syncthreads();
        if (tid == 0) {
            float s = __expf(dl - m);       // diagonal term (u_ii = dl)
            #pragma unroll
            for (int i = 0; i < NWARPS; i++) s += s_sum[i];
            g_row_loss[row] = m + logf(s) - dl;
        }
    } else {
        // robust fallback: full-row online LSE re-read (adversarial data only)
        float mt = -CUDART_INF_F, st = 0.f;
        for (int v = tid; v < KV4; v += NTHREADS) {
            float4 x = rp[v];
            float c[4] = {x.x, x.y, x.z, x.w};
            #pragma unroll
            for (int q = 0; q < 4; q++) {
                int   j = v * 4 + q;
                float u = (j == row) ? dl : c[q] * __expf(c[q]) * inv;
                float nm = fmaxf(mt, u);
                st = st * __expf(mt - nm) + __expf(u - nm);
                mt = nm;
            }
        }
        #pragma unroll
        for (int o = 16; o; o >>= 1) {
            float om = __shfl_xor_sync(0xffffffffu, mt, o);
            float os = __shfl_xor_sync(0xffffffffu, st, o);
            float nm = fmaxf(mt, om);
            st = st * __expf(mt - nm) + os * __expf(om - nm);
            mt = nm;
        }
        if ((tid & 31) == 0) { s_sum[tid >> 5] = st; s_max[tid >> 5] = mt; }
        __syncthreads();
        if (tid == 0) {
            float m2 = -CUDART_INF_F, s2v = 0.f;
            #pragma unroll
            for (int i = 0; i < NWARPS; i++) m2 = fmaxf(m2, s_max[i]);
            #pragma unroll
            for (int i = 0; i < NWARPS; i++) s2v += s_sum[i] * __expf(s_max[i] - m2);
            g_row_loss[row] = m2 + logf(s2v) - dl;
        }
    }

    // reset row scratch for next graph replay; count finished rows
    if (tid == 0) {
        g_candn[row]   = 0;
        g_rowdone[row] = 0;
        __threadfence();
        unsigned t2 = atomicAdd(&g_done, 1u);
        s_last = (t2 == (unsigned)(BSZ - 1));
    }
    __syncthreads();

    if (s_last) {
        float v = 0.f;
        #pragma unroll
        for (int i = tid; i < BSZ; i += NTHREADS) v += __ldcg(&g_row_loss[i]);
        #pragma unroll
        for (int o = 16; o; o >>= 1) v += __shfl_xor_sync(0xffffffffu, v, o);
        if ((tid & 31) == 0) s_sum[tid >> 5] = v;
        __syncthreads();
        if (tid == 0) {
            float t = 0.f;
            #pragma unroll
            for (int i = 0; i < NWARPS; i++) t += s_sum[i];
            out[0] = t * (1.0f / (float)BSZ);
            g_done = 0;                     // reset for next graph replay
        }
    }
}

extern "C" void kernel_launch(void* const* d_in, const int* in_sizes, int n_in,
                              void* d_out, int out_size)
{
    const float* logits = (const float*)d_in[0];
    (void)in_sizes; (void)n_in; (void)out_size;
    wl_row_kernel<<<2 * BSZ, NTHREADS>>>(logits, (float*)d_out);
}

// round 15
// speedup vs baseline: 1.0611x; 1.0611x over previous
#include <cuda_runtime.h>
#include <math_constants.h>

#define BSZ      1024
#define KCOLS    66560              // BSZ + 65536
#define KV4      (KCOLS / 4)        // 16640 float4 per row
#define HALF_F4  (KV4 / 2)          // 8320 float4 per half-row
#define NTHREADS 256
#define NWARPS   (NTHREADS / 32)
#define NFULL    568                // rows 0..567: one full-row CTA each
#define NHALFR   (BSZ - NFULL)      // rows 568..1023: two half-row CTAs each
#define FB       8                  // full path: 8 batches x 8 f4 = 64/thread
#define FREM     (FB * 8 * NTHREADS)        // 16384; 256 f4 remainder
#define HB       4                  // half path: 4 batches x 8 f4 = 32/thread
#define HREM     (HALF_F4 - HB * 8 * NTHREADS)  // 128 f4 remainder
#define VCAP     1408               // smem capture slots (both paths)
#define RCAP     1536               // per-row global candidate slots (half rows)
#define TCAND    2.5f

__device__ float    g_halfS[2 * BSZ];       // per-half partial sums
__device__ float4   g_candv[NHALFR * RCAP]; // per-split-row candidate vectors
__device__ int      g_candi[NHALFR * RCAP];
__device__ int      g_candn[NHALFR];        // counts (zero-init)
__device__ int      g_rowdone[NHALFR];      // completion counters (zero-init)
__device__ float    g_row_loss[BSZ];
__device__ unsigned g_done = 0;             // finished-row counter

__global__ __launch_bounds__(NTHREADS, 5) void wl_row_kernel(const float* __restrict__ logits,
                                                             float* __restrict__ out)
{
    __shared__ __align__(16) float4 s_vc[VCAP];
    __shared__ int   s_vi[VCAP];
    __shared__ int   s_cnt, s_base;
    __shared__ float s_sum[NWARPS];
    __shared__ float s_max[NWARPS];
    __shared__ float s_par[4];              // inv, m, dl, fast-flag
    __shared__ int   s_fin, s_last;

    const int tid = threadIdx.x;
    const int bid = (int)blockIdx.x;
    if (tid == 0) s_cnt = 0;
    __syncthreads();

    #define WL_DO(X, VIDX)                                                      \
    {                                                                           \
        a0 += __expf((X).x); a1 += __expf((X).y);                               \
        a2 += __expf((X).z); a3 += __expf((X).w);                               \
        float mx4 = fmaxf(fmaxf((X).x, (X).y), fmaxf((X).z, (X).w));            \
        if (mx4 >= TCAND) {                                                     \
            int p = atomicAdd(&s_cnt, 1);                                       \
            if (p < VCAP) { s_vc[p] = (X); s_vi[p] = (VIDX); }                  \
        }                                                                       \
    }
    #define WL_BATCH8(rp, vb)                                                   \
    {                                                                           \
        float4 x0 = (rp)[vb];                                                   \
        float4 x1 = (rp)[(vb) + 1 * NTHREADS];                                  \
        float4 x2 = (rp)[(vb) + 2 * NTHREADS];                                  \
        float4 x3 = (rp)[(vb) + 3 * NTHREADS];                                  \
        float4 x4 = (rp)[(vb) + 4 * NTHREADS];                                  \
        float4 x5 = (rp)[(vb) + 5 * NTHREADS];                                  \
        float4 x6 = (rp)[(vb) + 6 * NTHREADS];                                  \
        float4 x7 = (rp)[(vb) + 7 * NTHREADS];                                  \
        WL_DO(x0, (vb))                                                         \
        WL_DO(x1, (vb) + 1 * NTHREADS)                                          \
        WL_DO(x2, (vb) + 2 * NTHREADS)                                          \
        WL_DO(x3, (vb) + 3 * NTHREADS)                                          \
        WL_DO(x4, (vb) + 4 * NTHREADS)                                          \
        WL_DO(x5, (vb) + 5 * NTHREADS)                                          \
        WL_DO(x6, (vb) + 6 * NTHREADS)                                          \
        WL_DO(x7, (vb) + 7 * NTHREADS)                                          \
    }

    if (bid < NFULL) {
        // ======================= FULL-ROW PATH (R7 verbatim) ====================
        const int row = bid;
        const float4* __restrict__ rp =
            reinterpret_cast<const float4*>(logits + (size_t)row * KCOLS);

        float a0 = 0.f, a1 = 0.f, a2 = 0.f, a3 = 0.f;
        #pragma unroll 1
        for (int b = 0; b < FB; b++) {
            const int vb = tid + b * (8 * NTHREADS);
            WL_BATCH8(rp, vb)
        }
        for (int v = FREM + tid; v < KV4; v += NTHREADS) {
            float4 x = rp[v];
            WL_DO(x, v)
        }

        float sum = (a0 + a1) + (a2 + a3);
        #pragma unroll
        for (int o = 16; o; o >>= 1) sum += __shfl_xor_sync(0xffffffffu, sum, o);
        if ((tid & 31) == 0) s_sum[tid >> 5] = sum;
        __syncthreads();

        const int ncv = min(s_cnt, VCAP);
        float mxo = -CUDART_INF_F;
        for (int i = tid; i < ncv; i += NTHREADS) {
            float4 x = s_vc[i];
            const int base = s_vi[i] * 4;
            if (x.x >= TCAND && base + 0 != row) mxo = fmaxf(mxo, x.x);
            if (x.y >= TCAND && base + 1 != row) mxo = fmaxf(mxo, x.y);
            if (x.z >= TCAND && base + 2 != row) mxo = fmaxf(mxo, x.z);
            if (x.w >= TCAND && base + 3 != row) mxo = fmaxf(mxo, x.w);
        }
        #pragma unroll
        for (int o = 16; o; o >>= 1) mxo = fmaxf(mxo, __shfl_xor_sync(0xffffffffu, mxo, o));
        if ((tid & 31) == 0) s_max[tid >> 5] = mxo;
        __syncthreads();

        if (tid == 0) {
            float S = 0.f, M = -CUDART_INF_F;
            #pragma unroll
            for (int i = 0; i < NWARPS; i++) { S += s_sum[i]; M = fmaxf(M, s_max[i]); }
            float dl       = logits[(size_t)row * KCOLS + row];
            float neg_mean = (S - __expf(dl)) * (1.0f / (float)(KCOLS - 1));
            float inv      = 1.0f / neg_mean;
            float gmo = M * __expf(M) * inv;
            float m   = fmaxf(gmo, dl);
            float gT  = TCAND * __expf(TCAND) * inv;
            bool fast = (M >= TCAND) && (neg_mean > 0.f) &&
                        (gT <= m - 30.f) && (s_cnt <= VCAP);
            s_par[0] = inv; s_par[1] = m; s_par[2] = dl; s_par[3] = fast ? 1.f : 0.f;
        }
        __syncthreads();

        const float inv = s_par[0], m = s_par[1], dl = s_par[2];
        if (s_par[3] != 0.f) {
            float sl = 0.f;
            for (int i = tid; i < ncv; i += NTHREADS) {
                float4 x = s_vc[i];
                const int base = s_vi[i] * 4;
                if (x.x >= TCAND && base + 0 != row) sl += __expf(x.x * __expf(x.x) * inv - m);
                if (x.y >= TCAND && base + 1 != row) sl += __expf(x.y * __expf(x.y) * inv - m);
                if (x.z >= TCAND && base + 2 != row) sl += __expf(x.z * __expf(x.z) * inv - m);
                if (x.w >= TCAND && base + 3 != row) sl += __expf(x.w * __expf(x.w) * inv - m);
            }
            #pragma unroll
            for (int o = 16; o; o >>= 1) sl += __shfl_xor_sync(0xffffffffu, sl, o);
            if ((tid & 31) == 0) s_sum[tid >> 5] = sl;
            __syncthreads();
            if (tid == 0) {
                float s = __expf(dl - m);
                #pragma unroll
                for (int i = 0; i < NWARPS; i++) s += s_sum[i];
                g_row_loss[row] = m + logf(s) - dl;
            }
        } else {
            float mt = -CUDART_INF_F, st = 0.f;
            for (int v = tid; v < KV4; v += NTHREADS) {
                float4 x = rp[v];
                float c[4] = {x.x, x.y, x.z, x.w};
                #pragma unroll
                for (int q = 0; q < 4; q++) {
                    int   j = v * 4 + q;
                    float u = (j == row) ? dl : c[q] * __expf(c[q]) * inv;
                    float nm = fmaxf(mt, u);
                    st = st * __expf(mt - nm) + __expf(u - nm);
                    mt = nm;
                }
            }
            #pragma unroll
            for (int o = 16; o; o >>= 1) {
                float om = __shfl_xor_sync(0xffffffffu, mt, o);
                float os = __shfl_xor_sync(0xffffffffu, st, o);
                float nm = fmaxf(mt, om);
                st = st * __expf(mt - nm) + os * __expf(om - nm);
                mt = nm;
            }
            if ((tid & 31) == 0) { s_sum[tid >> 5] = st; s_max[tid >> 5] = mt; }
            __syncthreads();
            if (tid == 0) {
                float m2 = -CUDART_INF_F, s2v = 0.f;
                #pragma unroll
                for (int i = 0; i < NWARPS; i++) m2 = fmaxf(m2, s_max[i]);
                #pragma unroll
                for (int i = 0; i < NWARPS; i++) s2v += s_sum[i] * __expf(s_max[i] - m2);
                g_row_loss[row] = m2 + logf(s2v) - dl;
            }
        }
    } else {
        // ===================== HALF-ROW PATH (R14 machinery) ====================
        const int t    = bid - NFULL;           // 0..911
        const int rrel = t >> 1;                // 0..455
        const int row  = NFULL + rrel;
        const int half = t & 1;
        const float4* __restrict__ rp =
            reinterpret_cast<const float4*>(logits + (size_t)row * KCOLS);
        const int hbase = half * HALF_F4;

        float a0 = 0.f, a1 = 0.f, a2 = 0.f, a3 = 0.f;
        #pragma unroll 1
        for (int b = 0; b < HB; b++) {
            const int vb = hbase + tid + b * (8 * NTHREADS);
            WL_BATCH8(rp, vb)
        }
        if (tid < HREM) {
            const int v = hbase + HB * 8 * NTHREADS + tid;
            float4 x = rp[v];
            WL_DO(x, v)
        }

        float sum = (a0 + a1) + (a2 + a3);
        #pragma unroll
        for (int o = 16; o; o >>= 1) sum += __shfl_xor_sync(0xffffffffu, sum, o);
        if ((tid & 31) == 0) s_sum[tid >> 5] = sum;
        __syncthreads();

        const int cnt = s_cnt;
        if (tid == 0) {
            float Sh = 0.f;
            #pragma unroll
            for (int i = 0; i < NWARPS; i++) Sh += s_sum[i];
            g_halfS[2 * row + half] = Sh;
            int addn = (cnt <= VCAP) ? cnt : (RCAP + 1);    // poison on overflow
            s_base = (addn > 0) ? atomicAdd(&g_candn[rrel], addn) : 0;
        }
        __syncthreads();
        {
            const int ncopy = min(cnt, VCAP);
            const int base  = s_base;
            for (int i = tid; i < ncopy; i += NTHREADS) {
                const int idx = base + i;
                if (idx < RCAP) {
                    g_candv[(size_t)rrel * RCAP + idx] = s_vc[i];
                    g_candi[(size_t)rrel * RCAP + idx] = s_vi[i];
                }
            }
        }
        if (tid == 0) {
            __threadfence();
            int td = atomicAdd(&g_rowdone[rrel], 1);
            s_fin = (td == 1);
        }
        __syncthreads();
        if (!s_fin) return;

        const int cnt_raw = *((volatile int*)&g_candn[rrel]);
        const int ncv     = min(cnt_raw, RCAP);
        const float4* __restrict__ cv = &g_candv[(size_t)rrel * RCAP];
        const int*    __restrict__ ci = &g_candi[(size_t)rrel * RCAP];

        float mxo = -CUDART_INF_F;
        for (int i = tid; i < ncv; i += NTHREADS) {
            float4 x = __ldcg(&cv[i]);
            const int base = __ldcg(&ci[i]) * 4;
            if (x.x >= TCAND && base + 0 != row) mxo = fmaxf(mxo, x.x);
            if (x.y >= TCAND && base + 1 != row) mxo = fmaxf(mxo, x.y);
            if (x.z >= TCAND && base + 2 != row) mxo = fmaxf(mxo, x.z);
            if (x.w >= TCAND && base + 3 != row) mxo = fmaxf(mxo, x.w);
        }
        #pragma unroll
        for (int o = 16; o; o >>= 1) mxo = fmaxf(mxo, __shfl_xor_sync(0xffffffffu, mxo, o));
        if ((tid & 31) == 0) s_max[tid >> 5] = mxo;
        __syncthreads();

        if (tid == 0) {
            float M = -CUDART_INF_F;
            #pragma unroll
            for (int i = 0; i < NWARPS; i++) M = fmaxf(M, s_max[i]);
            float S = __ldcg(&g_halfS[2 * row]) + __ldcg(&g_halfS[2 * row + 1]);
            float dl = logits[(size_t)row * KCOLS + row];
            float neg_mean = (S - __expf(dl)) * (1.0f / (float)(KCOLS - 1));
            float inv = 1.0f / neg_mean;
            float gmo = M * __expf(M) * inv;
            float m   = fmaxf(gmo, dl);
            float gT  = TCAND * __expf(TCAND) * inv;
            bool fast = (M >= TCAND) && (neg_mean > 0.f) &&
                        (gT <= m - 30.f) && (cnt_raw <= RCAP);
            s_par[0] = inv; s_par[1] = m; s_par[2] = dl; s_par[3] = fast ? 1.f : 0.f;
        }
        __syncthreads();

        const float inv = s_par[0], m = s_par[1], dl = s_par[2];
        if (s_par[3] != 0.f) {
            float sl = 0.f;
            for (int i = tid; i < ncv; i += NTHREADS) {
                float4 x = __ldcg(&cv[i]);
                const int base = __ldcg(&ci[i]) * 4;
                if (x.x >= TCAND && base + 0 != row) sl += __expf(x.x * __expf(x.x) * inv - m);
                if (x.y >= TCAND && base + 1 != row) sl += __expf(x.y * __expf(x.y) * inv - m);
                if (x.z >= TCAND && base + 2 != row) sl += __expf(x.z * __expf(x.z) * inv - m);
                if (x.w >= TCAND && base + 3 != row) sl += __expf(x.w * __expf(x.w) * inv - m);
            }
            #pragma unroll
            for (int o = 16; o; o >>= 1) sl += __shfl_xor_sync(0xffffffffu, sl, o);
            if ((tid & 31) == 0) s_sum[tid >> 5] = sl;
            __syncthreads();
            if (tid == 0) {
                float s = __expf(dl - m);
                #pragma unroll
                for (int i = 0; i < NWARPS; i++) s += s_sum[i];
                g_row_loss[row] = m + logf(s) - dl;
            }
        } else {
            float mt = -CUDART_INF_F, st = 0.f;
            for (int v = tid; v < KV4; v += NTHREADS) {
                float4 x = rp[v];
                float c[4] = {x.x, x.y, x.z, x.w};
                #pragma unroll
                for (int q = 0; q < 4; q++) {
                    int   j = v * 4 + q;
                    float u = (j == row) ? dl : c[q] * __expf(c[q]) * inv;
                    float nm = fmaxf(mt, u);
                    st = st * __expf(mt - nm) + __expf(u - nm);
                    mt = nm;
                }
            }
            #pragma unroll
            for (int o = 16; o; o >>= 1) {
                float om = __shfl_xor_sync(0xffffffffu, mt, o);
                float os = __shfl_xor_sync(0xffffffffu, st, o);
                float nm = fmaxf(mt, om);
                st = st * __expf(mt - nm) + os * __expf(om - nm);
                mt = nm;
            }
            if ((tid & 31) == 0) { s_sum[tid >> 5] = st; s_max[tid >> 5] = mt; }
            __syncthreads();
            if (tid == 0) {
                float m2 = -CUDART_INF_F, s2v = 0.f;
                #pragma unroll
                for (int i = 0; i < NWARPS; i++) m2 = fmaxf(m2, s_max[i]);
                #pragma unroll
                for (int i = 0; i < NWARPS; i++) s2v += s_sum[i] * __expf(s_max[i] - m2);
                g_row_loss[row] = m2 + logf(s2v) - dl;
            }
        }
        if (tid == 0) {                 // reset split-row scratch for replay
            g_candn[rrel]   = 0;
            g_rowdone[rrel] = 0;
        }
    }
    #undef WL_BATCH8
    #undef WL_DO

    // ---- Row complete; last of 1024 completed rows computes the final mean -----
    if (tid == 0) {
        __threadfence();
        unsigned t2 = atomicAdd(&g_done, 1u);
        s_last = (t2 == (unsigned)(BSZ - 1));
    }
    __syncthreads();
    if (s_last) {
        float v = 0.f;
        #pragma unroll
        for (int i = tid; i < BSZ; i += NTHREADS) v += __ldcg(&g_row_loss[i]);
        #pragma unroll
        for (int o = 16; o; o >>= 1) v += __shfl_xor_sync(0xffffffffu, v, o);
        if ((tid & 31) == 0) s_sum[tid >> 5] = v;
        __syncthreads();
        if (tid == 0) {
            float tt = 0.f;
            #pragma unroll
            for (int i = 0; i < NWARPS; i++) tt += s_sum[i];
            out[0] = tt * (1.0f / (float)BSZ);
            g_done = 0;                 // reset for next graph replay
        }
    }
}

extern "C" void kernel_launch(void* const* d_in, const int* in_sizes, int n_in,
                              void* d_out, int out_size)
{
    const float* logits = (const float*)d_in[0];
    (void)in_sizes; (void)n_in; (void)out_size;
    wl_row_kernel<<<NFULL + 2 * NHALFR, NTHREADS>>>(logits, (float*)d_out);
}

// round 16
// speedup vs baseline: 1.0727x; 1.0110x over previous
#include <cuda_runtime.h>
#include <math_constants.h>

#define BSZ      1024
#define KCOLS    66560              // BSZ + 65536
#define KV4      (KCOLS / 4)        // 16640 float4 per row = 65 per thread
#define NTHREADS 256
#define NWARPS   (NTHREADS / 32)
#define NBATCH   8                  // 8 batches x 8 float4 = 64/thread (16384)
#define REM_BASE (NBATCH * 8 * NTHREADS)   // 16384; +tid < 16640: 1 f4 remainder
#define VCAP     1408               // captured-vector slots (expect ~250-400 used)
#define TCAND    2.5f
#define L2E      1.4426950408889634f

__device__ float    g_row_loss[BSZ];
__device__ unsigned g_done = 0;     // reset by last block each launch -> replay-safe

__global__ __launch_bounds__(NTHREADS, 5) void wl_row_kernel(const float* __restrict__ logits,
                                                             float* __restrict__ out)
{
    const int row = blockIdx.x;
    const float4* __restrict__ rp =
        reinterpret_cast<const float4*>(logits + (size_t)row * KCOLS);

    __shared__ __align__(16) float4 s_vc[VCAP];   // captured vectors (22.5 KB)
    __shared__ int   s_vi[VCAP];                  // their float4 indices (5.6 KB)
    __shared__ int   s_cnt;
    __shared__ float s_sum[NWARPS];
    __shared__ float s_max[NWARPS];
    __shared__ float s_par[4];                    // inv, m, dl, fast-flag
    __shared__ int   s_last;

    const int tid = threadIdx.x;
    if (tid == 0) s_cnt = 0;
    __syncthreads();

    // ---- Pass 1: 8-deep LDG.128 batches + packed f32x2 mul/add, MUFU ex2 -------
    unsigned long long acc01, acc23, l2e2;
    asm("mov.b64 %0, {%1, %2};" : "=l"(l2e2)  : "f"(L2E), "f"(L2E));
    asm("mov.b64 %0, {%1, %2};" : "=l"(acc01) : "f"(0.f), "f"(0.f));
    asm("mov.b64 %0, {%1, %2};" : "=l"(acc23) : "f"(0.f), "f"(0.f));

    #define WL_DO(X, VIDX)                                                      \
    {                                                                           \
        unsigned long long p01, p23, y01, y23, e01, e23;                        \
        float y0, y1, y2, y3, e0, e1, e2, e3;                                   \
        asm("mov.b64 %0, {%1, %2};" : "=l"(p01) : "f"((X).x), "f"((X).y));      \
        asm("mov.b64 %0, {%1, %2};" : "=l"(p23) : "f"((X).z), "f"((X).w));      \
        asm("mul.rn.f32x2 %0, %1, %2;" : "=l"(y01) : "l"(p01), "l"(l2e2));      \
        asm("mul.rn.f32x2 %0, %1, %2;" : "=l"(y23) : "l"(p23), "l"(l2e2));      \
        asm("mov.b64 {%0, %1}, %2;" : "=f"(y0), "=f"(y1) : "l"(y01));           \
        asm("mov.b64 {%0, %1}, %2;" : "=f"(y2), "=f"(y3) : "l"(y23));           \
        asm("ex2.approx.ftz.f32 %0, %1;" : "=f"(e0) : "f"(y0));                 \
        asm("ex2.approx.ftz.f32 %0, %1;" : "=f"(e1) : "f"(y1));                 \
        asm("ex2.approx.ftz.f32 %0, %1;" : "=f"(e2) : "f"(y2));                 \
        asm("ex2.approx.ftz.f32 %0, %1;" : "=f"(e3) : "f"(y3));                 \
        asm("mov.b64 %0, {%1, %2};" : "=l"(e01) : "f"(e0), "f"(e1));            \
        asm("mov.b64 %0, {%1, %2};" : "=l"(e23) : "f"(e2), "f"(e3));            \
        asm("add.rn.f32x2 %0, %1, %2;" : "=l"(acc01) : "l"(acc01), "l"(e01));   \
        asm("add.rn.f32x2 %0, %1, %2;" : "=l"(acc23) : "l"(acc23), "l"(e23));   \
        float mx4 = fmaxf(fmaxf((X).x, (X).y), fmaxf((X).z, (X).w));            \
        if (mx4 >= TCAND) {                                                     \
            int p = atomicAdd(&s_cnt, 1);                                       \
            if (p < VCAP) { s_vc[p] = (X); s_vi[p] = (VIDX); }                  \
        }                                                                       \
    }

    #pragma unroll 1
    for (int b = 0; b < NBATCH; b++) {
        const int vb = tid + b * (8 * NTHREADS);
        float4 x0 = rp[vb];
        float4 x1 = rp[vb + 1 * NTHREADS];
        float4 x2 = rp[vb + 2 * NTHREADS];
        float4 x3 = rp[vb + 3 * NTHREADS];
        float4 x4 = rp[vb + 4 * NTHREADS];
        float4 x5 = rp[vb + 5 * NTHREADS];
        float4 x6 = rp[vb + 6 * NTHREADS];
        float4 x7 = rp[vb + 7 * NTHREADS];
        WL_DO(x0, vb)
        WL_DO(x1, vb + 1 * NTHREADS)
        WL_DO(x2, vb + 2 * NTHREADS)
        WL_DO(x3, vb + 3 * NTHREADS)
        WL_DO(x4, vb + 4 * NTHREADS)
        WL_DO(x5, vb + 5 * NTHREADS)
        WL_DO(x6, vb + 6 * NTHREADS)
        WL_DO(x7, vb + 7 * NTHREADS)
    }
    {   // remainder: exactly one float4 per thread (16384 + tid < 16640)
        const int v = REM_BASE + tid;
        float4 x = rp[v];
        WL_DO(x, v)
    }
    #undef WL_DO

    float a0, a1, a2, a3;
    asm("mov.b64 {%0, %1}, %2;" : "=f"(a0), "=f"(a1) : "l"(acc01));
    asm("mov.b64 {%0, %1}, %2;" : "=f"(a2), "=f"(a3) : "l"(acc23));
    float sum = (a0 + a1) + (a2 + a3);
    #pragma unroll
    for (int o = 16; o; o >>= 1) sum += __shfl_xor_sync(0xffffffffu, sum, o);
    if ((tid & 31) == 0) s_sum[tid >> 5] = sum;
    __syncthreads();

    // ---- Filter stage (smem-only): exact off-diag max over true candidates ----
    const int ncv = min(s_cnt, VCAP);
    float mxo = -CUDART_INF_F;
    for (int i = tid; i < ncv; i += NTHREADS) {
        float4 x = s_vc[i];
        const int base = s_vi[i] * 4;
        if (x.x >= TCAND && base + 0 != row) mxo = fmaxf(mxo, x.x);
        if (x.y >= TCAND && base + 1 != row) mxo = fmaxf(mxo, x.y);
        if (x.z >= TCAND && base + 2 != row) mxo = fmaxf(mxo, x.z);
        if (x.w >= TCAND && base + 3 != row) mxo = fmaxf(mxo, x.w);
    }
    #pragma unroll
    for (int o = 16; o; o >>= 1) mxo = fmaxf(mxo, __shfl_xor_sync(0xffffffffu, mxo, o));
    if ((tid & 31) == 0) s_max[tid >> 5] = mxo;
    __syncthreads();

    if (tid == 0) {
        float S = 0.f, M = -CUDART_INF_F;
        #pragma unroll
        for (int i = 0; i < NWARPS; i++) { S += s_sum[i]; M = fmaxf(M, s_max[i]); }
        float dl       = logits[(size_t)row * KCOLS + row];     // cache hit
        float neg_mean = (S - __expf(dl)) * (1.0f / (float)(KCOLS - 1));
        float inv      = 1.0f / neg_mean;
        // g(l)=l*exp(l)*inv monotone for l >= -1; M >= TCAND > 0 on fast path, so
        // g(M) is the EXACT off-diagonal max of u. Row max m = max(g(M), dl).
        float gmo = M * __expf(M) * inv;
        float m   = fmaxf(gmo, dl);
        float gT  = TCAND * __expf(TCAND) * inv;  // bound on any non-candidate u
        bool fast = (M >= TCAND) && (neg_mean > 0.f) &&
                    (gT <= m - 30.f) && (s_cnt <= VCAP);
        s_par[0] = inv; s_par[1] = m; s_par[2] = dl; s_par[3] = fast ? 1.f : 0.f;
    }
    __syncthreads();

    const float inv = s_par[0], m = s_par[1], dl = s_par[2];
    const bool  fastp = (s_par[3] != 0.f);

    if (fastp) {
        // ---- Pass 2 (fast): filtered candidates from smem — zero re-read -------
        float sl = 0.f;
        for (int i = tid; i < ncv; i += NTHREADS) {
            float4 x = s_vc[i];
            const int base = s_vi[i] * 4;
            if (x.x >= TCAND && base + 0 != row) sl += __expf(x.x * __expf(x.x) * inv - m);
            if (x.y >= TCAND && base + 1 != row) sl += __expf(x.y * __expf(x.y) * inv - m);
            if (x.z >= TCAND && base + 2 != row) sl += __expf(x.z * __expf(x.z) * inv - m);
            if (x.w >= TCAND && base + 3 != row) sl += __expf(x.w * __expf(x.w) * inv - m);
        }
        #pragma unroll
        for (int o = 16; o; o >>= 1) sl += __shfl_xor_sync(0xffffffffu, sl, o);
        if ((tid & 31) == 0) s_sum[tid >> 5] = sl;
        __syncthreads();
        if (tid == 0) {
            float s = __expf(dl - m);             // diagonal term (u_ii = dl)
            #pragma unroll
            for (int i = 0; i < NWARPS; i++) s += s_sum[i];
            g_row_loss[row] = m + logf(s) - dl;
        }
    } else {
        // ---- Pass 2 (robust fallback): full online-LSE re-read ------------------
        float mt = -CUDART_INF_F, st = 0.f;
        for (int v = tid; v < KV4; v += NTHREADS) {
            float4 x = rp[v];
            float c[4] = {x.x, x.y, x.z, x.w};
            #pragma unroll
            for (int q = 0; q < 4; q++) {
                int   j = v * 4 + q;
                float u = (j == row) ? dl : c[q] * __expf(c[q]) * inv;
                float nm = fmaxf(mt, u);
                st = st * __expf(mt - nm) + __expf(u - nm);
                mt = nm;
            }
        }
        #pragma unroll
        for (int o = 16; o; o >>= 1) {
            float om = __shfl_xor_sync(0xffffffffu, mt, o);
            float os = __shfl_xor_sync(0xffffffffu, st, o);
            float nm = fmaxf(mt, om);
            st = st * __expf(mt - nm) + os * __expf(om - nm);
            mt = nm;
        }
        if ((tid & 31) == 0) { s_sum[tid >> 5] = st; s_max[tid >> 5] = mt; }
        __syncthreads();
        if (tid == 0) {
            float m2 = -CUDART_INF_F, s2v = 0.f;
            #pragma unroll
            for (int i = 0; i < NWARPS; i++) m2 = fmaxf(m2, s_max[i]);
            #pragma unroll
            for (int i = 0; i < NWARPS; i++) s2v += s_sum[i] * __expf(s_max[i] - m2);
            g_row_loss[row] = m2 + logf(s2v) - dl;
        }
    }

    // ---- Fused final reduction: last finishing block sums the 1024 row losses --
    if (tid == 0) {
        __threadfence();
        unsigned t = atomicAdd(&g_done, 1u);
        s_last = (t == (unsigned)(gridDim.x - 1));
    }
    __syncthreads();
    if (s_last) {
        float v = 0.f;
        #pragma unroll
        for (int i = tid; i < BSZ; i += NTHREADS) v += __ldcg(&g_row_loss[i]);
        #pragma unroll
        for (int o = 16; o; o >>= 1) v += __shfl_xor_sync(0xffffffffu, v, o);
        if ((tid & 31) == 0) s_sum[tid >> 5] = v;
        __syncthreads();
        if (tid == 0) {
            float t = 0.f;
            #pragma unroll
            for (int i = 0; i < NWARPS; i++) t += s_sum[i];
            out[0] = t * (1.0f / (float)BSZ);
            g_done = 0;                           // reset for next graph replay
        }
    }
}

extern "C" void kernel_launch(void* const* d_in, const int* in_sizes, int n_in,
                              void* d_out, int out_size)
{
    const float* logits = (const float*)d_in[0];
    (void)in_sizes; (void)n_in; (void)out_size;
    wl_row_kernel<<<BSZ, NTHREADS>>>(logits, (float*)d_out);
}

// round 17
// speedup vs baseline: 1.1066x; 1.0316x over previous
#include <cuda_runtime.h>
#include <math_constants.h>

#define BSZ      1024
#define KCOLS    66560              // BSZ + 65536
#define KV4      (KCOLS / 4)        // 16640 float4 per row
#define HALF_F4  (KV4 / 2)          // 8320 float4 per half-row
#define NTHREADS 256
#define NWARPS   (NTHREADS / 32)
#define NFULL    568                // rows 0..567: one full-row CTA each
#define NHALFR   (BSZ - NFULL)      // rows 568..1023: two half-row CTAs each
#define FB       8                  // full path: 8 batches x 8 f4 = 64/thread
#define FREM     (FB * 8 * NTHREADS)            // 16384; 256 f4 remainder
#define HB       4                  // half path: 4 batches x 8 f4 = 32/thread
#define HREM     (HALF_F4 - HB * 8 * NTHREADS)  // 128 f4 remainder
#define VCAP     1408               // smem capture slots (both paths)
#define RCAP     1536               // per-row global candidate slots (half rows)
#define TCAND    2.5f
#define L2E      1.4426950408889634f

__device__ float    g_halfS[2 * BSZ];       // per-half partial sums
__device__ float4   g_candv[NHALFR * RCAP]; // per-split-row candidate vectors
__device__ int      g_candi[NHALFR * RCAP];
__device__ int      g_candn[NHALFR];        // counts (zero-init)
__device__ int      g_rowdone[NHALFR];      // completion counters (zero-init)
__device__ float    g_row_loss[BSZ];
__device__ unsigned g_done = 0;             // finished-row counter

__global__ __launch_bounds__(NTHREADS, 5) void wl_row_kernel(const float* __restrict__ logits,
                                                             float* __restrict__ out)
{
    __shared__ __align__(16) float4 s_vc[VCAP];
    __shared__ int   s_vi[VCAP];
    __shared__ int   s_cnt, s_base;
    __shared__ float s_sum[NWARPS];
    __shared__ float s_max[NWARPS];
    __shared__ float s_par[4];              // inv, m, dl, fast-flag
    __shared__ int   s_fin, s_last;

    const int tid = threadIdx.x;
    const int bid = (int)blockIdx.x;
    if (tid == 0) s_cnt = 0;
    __syncthreads();

    // Packed-f32x2 streaming body (R16-verified): ~12 slots per float4
    #define WL_DO(X, VIDX)                                                      \
    {                                                                           \
        unsigned long long p01, p23, y01, y23, e01, e23;                        \
        float y0, y1, y2, y3, e0, e1, e2, e3;                                   \
        asm("mov.b64 %0, {%1, %2};" : "=l"(p01) : "f"((X).x), "f"((X).y));      \
        asm("mov.b64 %0, {%1, %2};" : "=l"(p23) : "f"((X).z), "f"((X).w));      \
        asm("mul.rn.f32x2 %0, %1, %2;" : "=l"(y01) : "l"(p01), "l"(l2e2));      \
        asm("mul.rn.f32x2 %0, %1, %2;" : "=l"(y23) : "l"(p23), "l"(l2e2));      \
        asm("mov.b64 {%0, %1}, %2;" : "=f"(y0), "=f"(y1) : "l"(y01));           \
        asm("mov.b64 {%0, %1}, %2;" : "=f"(y2), "=f"(y3) : "l"(y23));           \
        asm("ex2.approx.ftz.f32 %0, %1;" : "=f"(e0) : "f"(y0));                 \
        asm("ex2.approx.ftz.f32 %0, %1;" : "=f"(e1) : "f"(y1));                 \
        asm("ex2.approx.ftz.f32 %0, %1;" : "=f"(e2) : "f"(y2));                 \
        asm("ex2.approx.ftz.f32 %0, %1;" : "=f"(e3) : "f"(y3));                 \
        asm("mov.b64 %0, {%1, %2};" : "=l"(e01) : "f"(e0), "f"(e1));            \
        asm("mov.b64 %0, {%1, %2};" : "=l"(e23) : "f"(e2), "f"(e3));            \
        asm("add.rn.f32x2 %0, %1, %2;" : "=l"(acc01) : "l"(acc01), "l"(e01));   \
        asm("add.rn.f32x2 %0, %1, %2;" : "=l"(acc23) : "l"(acc23), "l"(e23));   \
        float mx4 = fmaxf(fmaxf((X).x, (X).y), fmaxf((X).z, (X).w));            \
        if (mx4 >= TCAND) {                                                     \
            int p = atomicAdd(&s_cnt, 1);                                       \
            if (p < VCAP) { s_vc[p] = (X); s_vi[p] = (VIDX); }                  \
        }                                                                       \
    }
    #define WL_BATCH8(rp, vb)                                                   \
    {                                                                           \
        float4 x0 = (rp)[vb];                                                   \
        float4 x1 = (rp)[(vb) + 1 * NTHREADS];                                  \
        float4 x2 = (rp)[(vb) + 2 * NTHREADS];                                  \
        float4 x3 = (rp)[(vb) + 3 * NTHREADS];                                  \
        float4 x4 = (rp)[(vb) + 4 * NTHREADS];                                  \
        float4 x5 = (rp)[(vb) + 5 * NTHREADS];                                  \
        float4 x6 = (rp)[(vb) + 6 * NTHREADS];                                  \
        float4 x7 = (rp)[(vb) + 7 * NTHREADS];                                  \
        WL_DO(x0, (vb))                                                         \
        WL_DO(x1, (vb) + 1 * NTHREADS)                                          \
        WL_DO(x2, (vb) + 2 * NTHREADS)                                          \
        WL_DO(x3, (vb) + 3 * NTHREADS)                                          \
        WL_DO(x4, (vb) + 4 * NTHREADS)                                          \
        WL_DO(x5, (vb) + 5 * NTHREADS)                                          \
        WL_DO(x6, (vb) + 6 * NTHREADS)                                          \
        WL_DO(x7, (vb) + 7 * NTHREADS)                                          \
    }
    #define WL_ACC_INIT                                                         \
        unsigned long long acc01, acc23, l2e2;                                  \
        asm("mov.b64 %0, {%1, %2};" : "=l"(l2e2)  : "f"(L2E), "f"(L2E));        \
        asm("mov.b64 %0, {%1, %2};" : "=l"(acc01) : "f"(0.f), "f"(0.f));        \
        asm("mov.b64 %0, {%1, %2};" : "=l"(acc23) : "f"(0.f), "f"(0.f));
    #define WL_ACC_SUM(sumv)                                                    \
        float a0, a1, a2, a3;                                                   \
        asm("mov.b64 {%0, %1}, %2;" : "=f"(a0), "=f"(a1) : "l"(acc01));         \
        asm("mov.b64 {%0, %1}, %2;" : "=f"(a2), "=f"(a3) : "l"(acc23));         \
        float sumv = (a0 + a1) + (a2 + a3);

    if (bid < NFULL) {
        // ======================= FULL-ROW PATH =================================
        const int row = bid;
        const float4* __restrict__ rp =
            reinterpret_cast<const float4*>(logits + (size_t)row * KCOLS);

        WL_ACC_INIT
        #pragma unroll 1
        for (int b = 0; b < FB; b++) {
            const int vb = tid + b * (8 * NTHREADS);
            WL_BATCH8(rp, vb)
        }
        for (int v = FREM + tid; v < KV4; v += NTHREADS) {
            float4 x = rp[v];
            WL_DO(x, v)
        }
        WL_ACC_SUM(sum)
        #pragma unroll
        for (int o = 16; o; o >>= 1) sum += __shfl_xor_sync(0xffffffffu, sum, o);
        if ((tid & 31) == 0) s_sum[tid >> 5] = sum;
        __syncthreads();

        const int ncv = min(s_cnt, VCAP);
        float mxo = -CUDART_INF_F;
        for (int i = tid; i < ncv; i += NTHREADS) {
            float4 x = s_vc[i];
            const int base = s_vi[i] * 4;
            if (x.x >= TCAND && base + 0 != row) mxo = fmaxf(mxo, x.x);
            if (x.y >= TCAND && base + 1 != row) mxo = fmaxf(mxo, x.y);
            if (x.z >= TCAND && base + 2 != row) mxo = fmaxf(mxo, x.z);
            if (x.w >= TCAND && base + 3 != row) mxo = fmaxf(mxo, x.w);
        }
        #pragma unroll
        for (int o = 16; o; o >>= 1) mxo = fmaxf(mxo, __shfl_xor_sync(0xffffffffu, mxo, o));
        if ((tid & 31) == 0) s_max[tid >> 5] = mxo;
        __syncthreads();

        if (tid == 0) {
            float S = 0.f, M = -CUDART_INF_F;
            #pragma unroll
            for (int i = 0; i < NWARPS; i++) { S += s_sum[i]; M = fmaxf(M, s_max[i]); }
            float dl       = logits[(size_t)row * KCOLS + row];
            float neg_mean = (S - __expf(dl)) * (1.0f / (float)(KCOLS - 1));
            float inv      = 1.0f / neg_mean;
            float gmo = M * __expf(M) * inv;
            float m   = fmaxf(gmo, dl);
            float gT  = TCAND * __expf(TCAND) * inv;
            bool fast = (M >= TCAND) && (neg_mean > 0.f) &&
                        (gT <= m - 30.f) && (s_cnt <= VCAP);
            s_par[0] = inv; s_par[1] = m; s_par[2] = dl; s_par[3] = fast ? 1.f : 0.f;
        }
        __syncthreads();

        const float inv = s_par[0], m = s_par[1], dl = s_par[2];
        if (s_par[3] != 0.f) {
            float sl = 0.f;
            for (int i = tid; i < ncv; i += NTHREADS) {
                float4 x = s_vc[i];
                const int base = s_vi[i] * 4;
                if (x.x >= TCAND && base + 0 != row) sl += __expf(x.x * __expf(x.x) * inv - m);
                if (x.y >= TCAND && base + 1 != row) sl += __expf(x.y * __expf(x.y) * inv - m);
                if (x.z >= TCAND && base + 2 != row) sl += __expf(x.z * __expf(x.z) * inv - m);
                if (x.w >= TCAND && base + 3 != row) sl += __expf(x.w * __expf(x.w) * inv - m);
            }
            #pragma unroll
            for (int o = 16; o; o >>= 1) sl += __shfl_xor_sync(0xffffffffu, sl, o);
            if ((tid & 31) == 0) s_sum[tid >> 5] = sl;
            __syncthreads();
            if (tid == 0) {
                float s = __expf(dl - m);
                #pragma unroll
                for (int i = 0; i < NWARPS; i++) s += s_sum[i];
                g_row_loss[row] = m + logf(s) - dl;
            }
        } else {
            float mt = -CUDART_INF_F, st = 0.f;
            for (int v = tid; v < KV4; v += NTHREADS) {
                float4 x = rp[v];
                float c[4] = {x.x, x.y, x.z, x.w};
                #pragma unroll
                for (int q = 0; q < 4; q++) {
                    int   j = v * 4 + q;
                    float u = (j == row) ? dl : c[q] * __expf(c[q]) * inv;
                    float nm = fmaxf(mt, u);
                    st = st * __expf(mt - nm) + __expf(u - nm);
                    mt = nm;
                }
            }
            #pragma unroll
            for (int o = 16; o; o >>= 1) {
                float om = __shfl_xor_sync(0xffffffffu, mt, o);
                float os = __shfl_xor_sync(0xffffffffu, st, o);
                float nm = fmaxf(mt, om);
                st = st * __expf(mt - nm) + os * __expf(om - nm);
                mt = nm;
            }
            if ((tid & 31) == 0) { s_sum[tid >> 5] = st; s_max[tid >> 5] = mt; }
            __syncthreads();
            if (tid == 0) {
                float m2 = -CUDART_INF_F, s2v = 0.f;
                #pragma unroll
                for (int i = 0; i < NWARPS; i++) m2 = fmaxf(m2, s_max[i]);
                #pragma unroll
                for (int i = 0; i < NWARPS; i++) s2v += s_sum[i] * __expf(s_max[i] - m2);
                g_row_loss[row] = m2 + logf(s2v) - dl;
            }
        }
    } else {
        // ===================== HALF-ROW PATH ====================================
        const int t    = bid - NFULL;           // 0..911
        const int rrel = t >> 1;                // 0..455
        const int row  = NFULL + rrel;
        const int half = t & 1;
        const float4* __restrict__ rp =
            reinterpret_cast<const float4*>(logits + (size_t)row * KCOLS);
        const int hbase = half * HALF_F4;

        WL_ACC_INIT
        #pragma unroll 1
        for (int b = 0; b < HB; b++) {
            const int vb = hbase + tid + b * (8 * NTHREADS);
            WL_BATCH8(rp, vb)
        }
        if (tid < HREM) {
            const int v = hbase + HB * 8 * NTHREADS + tid;
            float4 x = rp[v];
            WL_DO(x, v)
        }
        WL_ACC_SUM(sum)
        #pragma unroll
        for (int o = 16; o; o >>= 1) sum += __shfl_xor_sync(0xffffffffu, sum, o);
        if ((tid & 31) == 0) s_sum[tid >> 5] = sum;
        __syncthreads();

        const int cnt = s_cnt;
        if (tid == 0) {
            float Sh = 0.f;
            #pragma unroll
            for (int i = 0; i < NWARPS; i++) Sh += s_sum[i];
            g_halfS[2 * row + half] = Sh;
            int addn = (cnt <= VCAP) ? cnt : (RCAP + 1);    // poison on overflow
            s_base = (addn > 0) ? atomicAdd(&g_candn[rrel], addn) : 0;
        }
        __syncthreads();
        {
            const int ncopy = min(cnt, VCAP);
            const int base  = s_base;
            for (int i = tid; i < ncopy; i += NTHREADS) {
                const int idx = base + i;
                if (idx < RCAP) {
                    g_candv[(size_t)rrel * RCAP + idx] = s_vc[i];
                    g_candi[(size_t)rrel * RCAP + idx] = s_vi[i];
                }
            }
        }
        if (tid == 0) {
            __threadfence();
            int td = atomicAdd(&g_rowdone[rrel], 1);
            s_fin = (td == 1);
        }
        __syncthreads();
        if (!s_fin) return;

        const int cnt_raw = *((volatile int*)&g_candn[rrel]);
        const int ncv     = min(cnt_raw, RCAP);
        const float4* __restrict__ cv = &g_candv[(size_t)rrel * RCAP];
        const int*    __restrict__ ci = &g_candi[(size_t)rrel * RCAP];

        float mxo = -CUDART_INF_F;
        for (int i = tid; i < ncv; i += NTHREADS) {
            float4 x = __ldcg(&cv[i]);
            const int base = __ldcg(&ci[i]) * 4;
            if (x.x >= TCAND && base + 0 != row) mxo = fmaxf(mxo, x.x);
            if (x.y >= TCAND && base + 1 != row) mxo = fmaxf(mxo, x.y);
            if (x.z >= TCAND && base + 2 != row) mxo = fmaxf(mxo, x.z);
            if (x.w >= TCAND && base + 3 != row) mxo = fmaxf(mxo, x.w);
        }
        #pragma unroll
        for (int o = 16; o; o >>= 1) mxo = fmaxf(mxo, __shfl_xor_sync(0xffffffffu, mxo, o));
        if ((tid & 31) == 0) s_max[tid >> 5] = mxo;
        __syncthreads();

        if (tid == 0) {
            float M = -CUDART_INF_F;
            #pragma unroll
            for (int i = 0; i < NWARPS; i++) M = fmaxf(M, s_max[i]);
            float S = __ldcg(&g_halfS[2 * row]) + __ldcg(&g_halfS[2 * row + 1]);
            float dl = logits[(size_t)row * KCOLS + row];
            float neg_mean = (S - __expf(dl)) * (1.0f / (float)(KCOLS - 1));
            float inv = 1.0f / neg_mean;
            float gmo = M * __expf(M) * inv;
            float m   = fmaxf(gmo, dl);
            float gT  = TCAND * __expf(TCAND) * inv;
            bool fast = (M >= TCAND) && (neg_mean > 0.f) &&
                        (gT <= m - 30.f) && (cnt_raw <= RCAP);
            s_par[0] = inv; s_par[1] = m; s_par[2] = dl; s_par[3] = fast ? 1.f : 0.f;
        }
        __syncthreads();

        const float inv = s_par[0], m = s_par[1], dl = s_par[2];
        if (s_par[3] != 0.f) {
            float sl = 0.f;
            for (int i = tid; i < ncv; i += NTHREADS) {
                float4 x = __ldcg(&cv[i]);
                const int base = __ldcg(&ci[i]) * 4;
                if (x.x >= TCAND && base + 0 != row) sl += __expf(x.x * __expf(x.x) * inv - m);
                if (x.y >= TCAND && base + 1 != row) sl += __expf(x.y * __expf(x.y) * inv - m);
                if (x.z >= TCAND && base + 2 != row) sl += __expf(x.z * __expf(x.z) * inv - m);
                if (x.w >= TCAND && base + 3 != row) sl += __expf(x.w * __expf(x.w) * inv - m);
            }
            #pragma unroll
            for (int o = 16; o; o >>= 1) sl += __shfl_xor_sync(0xffffffffu, sl, o);
            if ((tid & 31) == 0) s_sum[tid >> 5] = sl;
            __syncthreads();
            if (tid == 0) {
                float s = __expf(dl - m);
                #pragma unroll
                for (int i = 0; i < NWARPS; i++) s += s_sum[i];
                g_row_loss[row] = m + logf(s) - dl;
            }
        } else {
            float mt = -CUDART_INF_F, st = 0.f;
            for (int v = tid; v < KV4; v += NTHREADS) {
                float4 x = rp[v];
                float c[4] = {x.x, x.y, x.z, x.w};
                #pragma unroll
                for (int q = 0; q < 4; q++) {
                    int   j = v * 4 + q;
                    float u = (j == row) ? dl : c[q] * __expf(c[q]) * inv;
                    float nm = fmaxf(mt, u);
                    st = st * __expf(mt - nm) + __expf(u - nm);
                    mt = nm;
                }
            }
            #pragma unroll
            for (int o = 16; o; o >>= 1) {
                float om = __shfl_xor_sync(0xffffffffu, mt, o);
                float os = __shfl_xor_sync(0xffffffffu, st, o);
                float nm = fmaxf(mt, om);
                st = st * __expf(mt - nm) + os * __expf(om - nm);
                mt = nm;
            }
            if ((tid & 31) == 0) { s_sum[tid >> 5] = st; s_max[tid >> 5] = mt; }
            __syncthreads();
            if (tid == 0) {
                float m2 = -CUDART_INF_F, s2v = 0.f;
                #pragma unroll
                for (int i = 0; i < NWARPS; i++) m2 = fmaxf(m2, s_max[i]);
                #pragma unroll
                for (int i = 0; i < NWARPS; i++) s2v += s_sum[i] * __expf(s_max[i] - m2);
                g_row_loss[row] = m2 + logf(s2v) - dl;
            }
        }
        if (tid == 0) {                 // reset split-row scratch for replay
            g_candn[rrel]   = 0;
            g_rowdone[rrel] = 0;
        }
    }
    #undef WL_ACC_SUM
    #undef WL_ACC_INIT
    #undef WL_BATCH8
    #undef WL_DO

    // ---- Row complete; last of 1024 completed rows computes the final mean -----
    if (tid == 0) {
        __threadfence();
        unsigned t2 = atomicAdd(&g_done, 1u);
        s_last = (t2 == (unsigned)(BSZ - 1));
    }
    __syncthreads();
    if (s_last) {
        float v = 0.f;
        #pragma unroll
        for (int i = tid; i < BSZ; i += NTHREADS) v += __ldcg(&g_row_loss[i]);
        #pragma unroll
        for (int o = 16; o; o >>= 1) v += __shfl_xor_sync(0xffffffffu, v, o);
        if ((tid & 31) == 0) s_sum[tid >> 5] = v;
        __syncthreads();
        if (tid == 0) {
            float tt = 0.f;
            #pragma unroll
            for (int i = 0; i < NWARPS; i++) tt += s_sum[i];
            out[0] = tt * (1.0f / (float)BSZ);
            g_done = 0;                 // reset for next graph replay
        }
    }
}

extern "C" void kernel_launch(void* const* d_in, const int* in_sizes, int n_in,
                              void* d_out, int out_size)
{
    const float* logits = (const float*)d_in[0];
    (void)in_sizes; (void)n_in; (void)out_size;
    wl_row_kernel<<<NFULL + 2 * NHALFR, NTHREADS>>>(logits, (float*)d_out);
}